// round 10
// baseline (speedup 1.0000x reference)
#include <cuda_runtime.h>
#include <cuda_fp16.h>
#include <math.h>

#define BB 8
#define CC 64
#define HH 128
#define WW 128
#define HW (HH*WW)
#define KK 9
#define CO 64
#define CK (CC*KK)   // 576

typedef unsigned int u32;

__device__ __half g_xth[BB*HW*CC];      // x NHWC fp16
__device__ float  g_off[BB*27*HW];      // planar offsets/masks
__device__ __half g_col[(size_t)BB*HW*CK]; // gathered col [b][px][t*64+c] fp16
__device__ __half g_wth[KK*CO*CC];      // dcn weights [t][co][c] fp16
__device__ __half g_woh[KK*32*CC];      // offset weights [t][o pad32][c] fp16

#define CSTRH 72
#define TP 128

// ---------------------------------------------------------------------------
// Kernel A: NCHW -> NHWC transpose (fp16 output)
// ---------------------------------------------------------------------------
__global__ void k_transpose(const float* __restrict__ x) {
    __shared__ float tile[32][33];
    int b  = blockIdx.z;
    int p0 = blockIdx.x * 32;
    int c0 = blockIdx.y * 32;
    int tx = threadIdx.x, ty = threadIdx.y;   // 32 x 8
    const float* xb = x + (size_t)b * CC * HW;
    #pragma unroll
    for (int i = 0; i < 32; i += 8)
        tile[ty + i][tx] = xb[(size_t)(c0 + ty + i) * HW + p0 + tx];
    __syncthreads();
    __half* xoh = g_xth + (size_t)b * HW * CC;
    #pragma unroll
    for (int i = 0; i < 32; i += 8)
        xoh[(size_t)(p0 + ty + i) * CC + c0 + tx] = __float2half(tile[tx][ty + i]);
}

// ---------------------------------------------------------------------------
// Kernel W: weight reorder/convert
// ---------------------------------------------------------------------------
__global__ void k_wreorder(const float* __restrict__ wd, const float* __restrict__ wo) {
    int idx = blockIdx.x * 256 + threadIdx.x;
    if (idx < KK * CO * CC) {
        int t  = idx >> 12;
        int co = (idx >> 6) & 63;
        int c  = idx & 63;
        g_wth[idx] = __float2half(wd[co * CK + c * KK + t]);
    }
    if (idx < KK * 32 * CC) {
        int t = idx >> 11;
        int o = (idx >> 6) & 31;
        int c = idx & 63;
        g_woh[idx] = __float2half(o < 27 ? wo[o * CK + c * KK + t] : 0.f);
    }
}

// ---------------------------------------------------------------------------
// Kernel B: offset conv via tensor cores
// ---------------------------------------------------------------------------
__global__ void __launch_bounds__(256, 3) k_offcv(const float* __restrict__ b_off) {
    extern __shared__ __half smh[];
    __half* col = smh;                    // 128 * 72 halves
    __half* wsO = smh + 128 * CSTRH;      // 32 * 72 halves

    int tid = threadIdx.x;
    int b   = blockIdx.y;
    int p0  = blockIdx.x * 128;
    int ho  = blockIdx.x;

    int g = tid >> 3, lane8 = tid & 7, cbase = lane8 * 8;
    const __half* xb = g_xth + (size_t)b * HW * CC;

    int lane = tid & 31, w = tid >> 5;
    int cobase = (w & 1) * 16;
    int pxh    = (w >> 1) * 32;
    int gid = lane >> 2, tig = lane & 3;

    float bl = (cobase + gid     < 27) ? b_off[cobase + gid]     : 0.f;
    float bh = (cobase + gid + 8 < 27) ? b_off[cobase + gid + 8] : 0.f;
    float acc[4][4];
    #pragma unroll
    for (int nt = 0; nt < 4; nt++) {
        acc[nt][0] = bl; acc[nt][1] = bl;
        acc[nt][2] = bh; acc[nt][3] = bh;
    }

    #pragma unroll 1
    for (int t = 0; t < 9; t++) {
        const u32* wsrc = (const u32*)(g_woh + t * 32 * CC);
        #pragma unroll
        for (int idx = tid; idx < 1024; idx += 256) {
            int o = idx >> 5, kp = idx & 31;
            *(u32*)&wsO[o * CSTRH + kp * 2] = wsrc[idx];
        }

        int dty = t / 3 - 1, dtx = t % 3 - 1;
        int y = ho + dty;
        bool vy = (y >= 0) & (y < HH);
        #pragma unroll
        for (int pass = 0; pass < 4; pass++) {
            int pi = pass * 32 + g;
            int xx = pi + dtx;
            uint4 v = make_uint4(0, 0, 0, 0);
            if (vy & (xx >= 0) & (xx < WW))
                v = *(const uint4*)(xb + ((size_t)(y * WW + xx)) * CC + cbase);
            *(uint4*)&col[pi * CSTRH + cbase] = v;
        }
        __syncthreads();

        #pragma unroll
        for (int ks = 0; ks < 4; ks++) {
            int kb = ks * 16 + 2 * tig;
            u32 a0 = *(u32*)&wsO[(cobase + gid)     * CSTRH + kb];
            u32 a1 = *(u32*)&wsO[(cobase + gid + 8) * CSTRH + kb];
            u32 a2 = *(u32*)&wsO[(cobase + gid)     * CSTRH + kb + 8];
            u32 a3 = *(u32*)&wsO[(cobase + gid + 8) * CSTRH + kb + 8];
            #pragma unroll
            for (int nt = 0; nt < 4; nt++) {
                const __half* brow = &col[(pxh + nt * 8 + gid) * CSTRH + kb];
                u32 b0 = *(const u32*)brow;
                u32 b1 = *(const u32*)(brow + 8);
                asm volatile(
                    "mma.sync.aligned.m16n8k16.row.col.f32.f16.f16.f32 "
                    "{%0,%1,%2,%3}, {%4,%5,%6,%7}, {%8,%9}, {%0,%1,%2,%3};"
                    : "+f"(acc[nt][0]), "+f"(acc[nt][1]),
                      "+f"(acc[nt][2]), "+f"(acc[nt][3])
                    : "r"(a0), "r"(a1), "r"(a2), "r"(a3), "r"(b0), "r"(b1));
            }
        }
        __syncthreads();
    }

    float* ob = g_off + (size_t)b * 27 * HW;
    #pragma unroll
    for (int nt = 0; nt < 4; nt++) {
        int wo_lo = pxh + nt * 8 + 2 * tig;
        int p = p0 + wo_lo;
        #pragma unroll
        for (int j = 0; j < 2; j++) {
            int o = cobase + gid + j * 8;
            if (o >= 27) continue;
            float v0 = acc[nt][j * 2], v1 = acc[nt][j * 2 + 1];
            if (o < 9) {
                float a = (float)(ho + o / 3 - 1);
                v0 += a; v1 += a;
            } else if (o < 18) {
                int tt = o - 9;
                float a = (float)(wo_lo + tt % 3 - 1);
                v0 += a; v1 += a + 1.f;
            } else {
                v0 = 1.f / (1.f + __expf(-v0));
                v1 = 1.f / (1.f + __expf(-v1));
            }
            *(float2*)(ob + (size_t)o * HW + p) = make_float2(v0, v1);
        }
    }
}

// ---------------------------------------------------------------------------
// Kernel G: pure streaming bilinear gather -> g_col (no smem, no barriers)
// ---------------------------------------------------------------------------
__global__ void __launch_bounds__(256) k_gather(int dummy) {
    int tid = threadIdx.x;
    int b   = blockIdx.y;
    int p0  = blockIdx.x * 32;

    int g = tid >> 3, lane8 = tid & 7, cbase = lane8 * 8;
    int px = p0 + g;
    const __half* xb = g_xth + (size_t)b * HW * CC;
    const float* offb = g_off + (size_t)b * 27 * HW;
    __half* cdst = g_col + ((size_t)(b * HW + px)) * CK + cbase;

    #pragma unroll 3
    for (int t = 0; t < 9; t++) {
        float py  = offb[(size_t)t * HW + px];
        float pxs = offb[(size_t)(9 + t) * HW + px];
        float mm  = offb[(size_t)(18 + t) * HW + px];
        float y0f = floorf(py), x0f = floorf(pxs);
        float dy = py - y0f, dx = pxs - x0f;
        int y0 = (int)y0f, x0 = (int)x0f;
        int y1 = y0 + 1,  x1 = x0 + 1;
        float wy0 = ((y0 >= 0) & (y0 < HH)) ? (1.f - dy) * mm : 0.f;
        float wy1 = ((y1 >= 0) & (y1 < HH)) ? dy * mm : 0.f;
        float wx0 = ((x0 >= 0) & (x0 < WW)) ? (1.f - dx) : 0.f;
        float wx1 = ((x1 >= 0) & (x1 < WW)) ? dx : 0.f;
        float w00 = wy0 * wx0, w01 = wy0 * wx1;
        float w10 = wy1 * wx0, w11 = wy1 * wx1;
        int y0c = min(max(y0, 0), HH - 1), y1c = min(max(y1, 0), HH - 1);
        int x0c = min(max(x0, 0), WW - 1), x1c = min(max(x1, 0), WW - 1);

        uint4 v00 = *(const uint4*)(xb + ((size_t)(y0c * WW + x0c)) * CC + cbase);
        uint4 v01 = *(const uint4*)(xb + ((size_t)(y0c * WW + x1c)) * CC + cbase);
        uint4 v10 = *(const uint4*)(xb + ((size_t)(y1c * WW + x0c)) * CC + cbase);
        uint4 v11 = *(const uint4*)(xb + ((size_t)(y1c * WW + x1c)) * CC + cbase);
        const __half2* h00 = (const __half2*)&v00;
        const __half2* h01 = (const __half2*)&v01;
        const __half2* h10 = (const __half2*)&v10;
        const __half2* h11 = (const __half2*)&v11;

        __half2 hh[4];
        #pragma unroll
        for (int q = 0; q < 4; q++) {
            float2 f00 = __half22float2(h00[q]);
            float2 f01 = __half22float2(h01[q]);
            float2 f10 = __half22float2(h10[q]);
            float2 f11 = __half22float2(h11[q]);
            float rx = w00 * f00.x + w01 * f01.x + w10 * f10.x + w11 * f11.x;
            float ry = w00 * f00.y + w01 * f01.y + w10 * f10.y + w11 * f11.y;
            hh[q] = __floats2half2_rn(rx, ry);
        }
        *(uint4*)(cdst + t * 64) = *(uint4*)hh;
    }
}

// ---------------------------------------------------------------------------
// Kernel M: GEMM col[128px][576] x W[576][64], double-buffered per tap.
// Tap chunk = 128px x 64 halves = 1024 uint4 -> 4 per thread:
//   flat = i*256+tid; pi = flat>>3 (0..127); grp = flat&7 (0..7, 8 halves each)
// ---------------------------------------------------------------------------
__global__ void __launch_bounds__(256, 3) k_gemm(const float* __restrict__ b_dcn,
                                                 float* __restrict__ out) {
    extern __shared__ __half smh[];
    __half* cb[2] = { smh, smh + TP * CSTRH };
    __half* wb[2] = { smh + 2 * TP * CSTRH, smh + 2 * TP * CSTRH + CO * CSTRH };

    int tid = threadIdx.x;
    int b   = blockIdx.y;
    int p0  = blockIdx.x * TP;

    int lane = tid & 31, w = tid >> 5;
    int cobase = (w & 3) * 16;
    int pxh    = (w >> 2) * 64;
    int gid = lane >> 2, tig = lane & 3;

    const __half* csrc = g_col + ((size_t)(b * HW + p0)) * CK;

    float acc[8][4];
    #pragma unroll
    for (int i = 0; i < 8; i++)
        #pragma unroll
        for (int j = 0; j < 4; j++) acc[i][j] = 0.f;

    // prologue: load tap 0 (col + weights) into buffer 0
    uint4 creg[4];
    #pragma unroll
    for (int i = 0; i < 4; i++) {
        int flat = i * 256 + tid;            // 0..1023
        int pi = flat >> 3, grp = flat & 7;  // pi 0..127, grp 0..7 (8 halves each)
        creg[i] = *(const uint4*)(csrc + (size_t)pi * CK + grp * 8);
        *(uint4*)&cb[0][pi * CSTRH + grp * 8] = creg[i];
    }
    {
        const u32* wsrc = (const u32*)(g_wth);
        #pragma unroll
        for (int idx = tid; idx < 2048; idx += 256) {
            int co = idx >> 5, kp = idx & 31;
            *(u32*)&wb[0][co * CSTRH + kp * 2] = wsrc[idx];
        }
    }
    __syncthreads();

    #pragma unroll 1
    for (int t = 0; t < 9; t++) {
        int cur = t & 1, nxt = cur ^ 1;

        // issue next tap's loads first (LDG in flight over the MMA)
        if (t < 8) {
            #pragma unroll
            for (int i = 0; i < 4; i++) {
                int flat = i * 256 + tid;
                int pi = flat >> 3, grp = flat & 7;
                creg[i] = *(const uint4*)(csrc + (size_t)pi * CK + (t + 1) * 64 + grp * 8);
            }
            const u32* wsrc = (const u32*)(g_wth + (t + 1) * CO * CC);
            #pragma unroll
            for (int idx = tid; idx < 2048; idx += 256) {
                int co = idx >> 5, kp = idx & 31;
                *(u32*)&wb[nxt][co * CSTRH + kp * 2] = wsrc[idx];
            }
        }

        // MMA on current buffers
        #pragma unroll
        for (int ks = 0; ks < 4; ks++) {
            int kb = ks * 16 + 2 * tig;
            u32 a0 = *(const u32*)&wb[cur][(cobase + gid)     * CSTRH + kb];
            u32 a1 = *(const u32*)&wb[cur][(cobase + gid + 8) * CSTRH + kb];
            u32 a2 = *(const u32*)&wb[cur][(cobase + gid)     * CSTRH + kb + 8];
            u32 a3 = *(const u32*)&wb[cur][(cobase + gid + 8) * CSTRH + kb + 8];
            #pragma unroll
            for (int nt = 0; nt < 8; nt++) {
                const __half* brow = &cb[cur][(pxh + nt * 8 + gid) * CSTRH + kb];
                u32 b0 = *(const u32*)brow;
                u32 b1 = *(const u32*)(brow + 8);
                asm volatile(
                    "mma.sync.aligned.m16n8k16.row.col.f32.f16.f16.f32 "
                    "{%0,%1,%2,%3}, {%4,%5,%6,%7}, {%8,%9}, {%0,%1,%2,%3};"
                    : "+f"(acc[nt][0]), "+f"(acc[nt][1]),
                      "+f"(acc[nt][2]), "+f"(acc[nt][3])
                    : "r"(a0), "r"(a1), "r"(a2), "r"(a3), "r"(b0), "r"(b1));
            }
        }

        // commit next col chunk to smem
        if (t < 8) {
            #pragma unroll
            for (int i = 0; i < 4; i++) {
                int flat = i * 256 + tid;
                int pi = flat >> 3, grp = flat & 7;
                *(uint4*)&cb[nxt][pi * CSTRH + grp * 8] = creg[i];
            }
        }
        __syncthreads();
    }

    float bl = b_dcn[cobase + gid];
    float bh = b_dcn[cobase + gid + 8];
    float* ob = out + (size_t)b * CO * HW + p0 + pxh + 2 * tig;
    #pragma unroll
    for (int nt = 0; nt < 8; nt++) {
        float2 vlo = make_float2(acc[nt][0] + bl, acc[nt][1] + bl);
        float2 vhi = make_float2(acc[nt][2] + bh, acc[nt][3] + bh);
        *(float2*)(ob + (size_t)(cobase + gid)     * HW + nt * 8) = vlo;
        *(float2*)(ob + (size_t)(cobase + gid + 8) * HW + nt * 8) = vhi;
    }
}

// ---------------------------------------------------------------------------
extern "C" void kernel_launch(void* const* d_in, const int* in_sizes, int n_in,
                              void* d_out, int out_size) {
    const float* x        = (const float*)d_in[0];
    const float* w_offset = (const float*)d_in[1];
    const float* b_offset = (const float*)d_in[2];
    const float* w_dcn    = (const float*)d_in[3];
    const float* b_dcn    = (const float*)d_in[4];
    float* out = (float*)d_out;

    const int SMEM_O = (128 * CSTRH + 32 * CSTRH) * 2;             // 23040
    const int SMEM_M = (2 * TP * CSTRH + 2 * CO * CSTRH) * 2;      // 55296
    cudaFuncSetAttribute(k_offcv, cudaFuncAttributeMaxDynamicSharedMemorySize, SMEM_O);
    cudaFuncSetAttribute(k_gemm,  cudaFuncAttributeMaxDynamicSharedMemorySize, SMEM_M);

    k_transpose<<<dim3(HW / 32, CC / 32, BB), dim3(32, 8)>>>(x);
    k_wreorder<<<(KK * CO * CC + 255) / 256, 256>>>(w_dcn, w_offset);
    k_offcv<<<dim3(HW / 128, BB), 256, SMEM_O>>>(b_offset);
    k_gather<<<dim3(HW / 32, BB), 256>>>(0);
    k_gemm<<<dim3(HW / TP, BB), 256, SMEM_M>>>(b_dcn, out);
}